// round 10
// baseline (speedup 1.0000x reference)
#include <cuda_runtime.h>
#include <cuda_bf16.h>
#include <math.h>

// ---------------- problem-size constants (fixed per dataset) ----------------
#define NMAX 100000
#define EMAX 3200000
#define F_IN 512
#define F_MID 16
#define F_OUT 64

// ---------------- scratch (static device allocations; no cudaMalloc) -------
__device__ int   g_is64;               // edge_index dtype flag (1 = int64)
__device__ int   g_cnt[NMAX];          // in-degree (excl self loop)
__device__ float g_dinv[NMAX];         // rsqrt(deg+1)
__device__ int   g_tile_pub[128];      // lookback: tile aggregate + 1 (0 = not ready)
__device__ int   g_rowptr[NMAX + 1];
__device__ int   g_cursor[NMAX];
__device__ int   g_col[EMAX];          // CSR source indices grouped by dst
__device__ __align__(16) float g_hp[NMAX * F_MID];    // (x@W1)*dinv
__device__ __align__(16) float g_h1p[NMAX * F_MID];   // relu(layer1)*dinv

// ---------------- init + dtype detection -------------------------------------
// JAX default config demotes int64 -> int32; detect which layout we actually
// got: if the first 16 int64 reads are all valid node ids, it's real int64.
__global__ void k_init_detect(const long long* __restrict__ ei, int n) {
    int i = blockIdx.x * blockDim.x + threadIdx.x;
    if (i < n) g_cnt[i] = 0;
    if (i < 128) g_tile_pub[i] = 0;
    if (i == 0) {
        bool ok64 = true;
        #pragma unroll
        for (int t = 0; t < 16; t++) {
            long long v = ei[t];
            if (v < 0 || v >= NMAX) ok64 = false;
        }
        g_is64 = ok64 ? 1 : 0;
    }
}

// ---------------- degree count (4 edges / thread) ---------------------------
__global__ void k_count(const void* __restrict__ ei, int E) {
    int e4 = (blockIdx.x * blockDim.x + threadIdx.x) * 4;
    if (e4 >= E) return;
    int d[4] = {-1, -1, -1, -1};
    if (e4 + 3 < E) {
        if (g_is64) {
            const long long* p = (const long long*)ei + (long long)E + e4;
            longlong2 v0 = *(const longlong2*)p;
            longlong2 v1 = *(const longlong2*)(p + 2);
            d[0] = (int)v0.x; d[1] = (int)v0.y; d[2] = (int)v1.x; d[3] = (int)v1.y;
        } else {
            int4 v = *(const int4*)((const int*)ei + E + e4);
            d[0] = v.x; d[1] = v.y; d[2] = v.z; d[3] = v.w;
        }
    } else {
        for (int j = 0; j < 4 && e4 + j < E; j++)
            d[j] = g_is64 ? (int)((const long long*)ei)[(long long)E + e4 + j]
                          : ((const int*)ei)[E + e4 + j];
    }
    #pragma unroll
    for (int j = 0; j < 4; j++)
        if ((unsigned)d[j] < NMAX) atomicAdd(&g_cnt[d[j]], 1);
}

// ---------------- single-pass scan with decoupled lookback ------------------
// Builds g_rowptr, g_cursor, g_dinv in one launch. 98 tiles of 1024 all fit in
// wave 1 (<=148 SMs), so spinning on lower-indexed tiles cannot deadlock.
// Publication uses a single word (total+1), so no fence is needed.
__global__ void k_scanAll(int n) {
    __shared__ int wsum[32];
    __shared__ int sprefix;
    const int lane = threadIdx.x & 31;
    const int wid  = threadIdx.x >> 5;
    const int b    = blockIdx.x;
    int idx = b * 1024 + threadIdx.x;
    int v = (idx < n) ? g_cnt[idx] : 0;
    if (idx < n) g_dinv[idx] = rsqrtf((float)(v + 1));  // +1 self loop

    int s = v;
    #pragma unroll
    for (int d = 1; d < 32; d <<= 1) {
        int t = __shfl_up_sync(0xffffffffu, s, d);
        if (lane >= d) s += t;
    }
    if (lane == 31) wsum[wid] = s;
    __syncthreads();
    if (wid == 0) {
        int w = wsum[lane];
        #pragma unroll
        for (int d = 1; d < 32; d <<= 1) {
            int t = __shfl_up_sync(0xffffffffu, w, d);
            if (lane >= d) w += t;
        }
        wsum[lane] = w;  // inclusive over warp sums
    }
    __syncthreads();
    if (wid > 0) s += wsum[wid - 1];
    // s = inclusive prefix within tile; tile total = wsum[31]

    if (threadIdx.x == 0) {
        ((volatile int*)g_tile_pub)[b] = wsum[31] + 1;  // publish aggregate
    }
    // lookback: warp 0 sums aggregates of tiles 0..b-1
    if (wid == 0) {
        int pre = 0;
        for (int j = lane; j < b; j += 32) {
            int p;
            do { p = ((volatile int*)g_tile_pub)[j]; } while (p == 0);
            pre += p - 1;
        }
        #pragma unroll
        for (int d = 16; d > 0; d >>= 1)
            pre += __shfl_xor_sync(0xffffffffu, pre, d);
        if (lane == 0) sprefix = pre;
    }
    __syncthreads();
    int excl = sprefix + s - v;
    if (idx < n) {
        g_rowptr[idx] = excl;
        g_cursor[idx] = excl;
        if (idx == n - 1) g_rowptr[n] = sprefix + s;
    }
}

// ---------------- CSR bucket fill (4 edges / thread) -------------------------
__global__ void k_fill(const void* __restrict__ ei, int E) {
    int e4 = (blockIdx.x * blockDim.x + threadIdx.x) * 4;
    if (e4 >= E) return;
    int s[4] = {-1, -1, -1, -1}, d[4] = {-1, -1, -1, -1};
    if (e4 + 3 < E) {
        if (g_is64) {
            const long long* ps = (const long long*)ei + e4;
            const long long* pd = (const long long*)ei + (long long)E + e4;
            longlong2 a0 = *(const longlong2*)ps;
            longlong2 a1 = *(const longlong2*)(ps + 2);
            longlong2 b0 = *(const longlong2*)pd;
            longlong2 b1 = *(const longlong2*)(pd + 2);
            s[0] = (int)a0.x; s[1] = (int)a0.y; s[2] = (int)a1.x; s[3] = (int)a1.y;
            d[0] = (int)b0.x; d[1] = (int)b0.y; d[2] = (int)b1.x; d[3] = (int)b1.y;
        } else {
            int4 vs = *(const int4*)((const int*)ei + e4);
            int4 vd = *(const int4*)((const int*)ei + E + e4);
            s[0] = vs.x; s[1] = vs.y; s[2] = vs.z; s[3] = vs.w;
            d[0] = vd.x; d[1] = vd.y; d[2] = vd.z; d[3] = vd.w;
        }
    } else {
        for (int j = 0; j < 4 && e4 + j < E; j++) {
            if (g_is64) {
                s[j] = (int)((const long long*)ei)[e4 + j];
                d[j] = (int)((const long long*)ei)[(long long)E + e4 + j];
            } else {
                s[j] = ((const int*)ei)[e4 + j];
                d[j] = ((const int*)ei)[E + e4 + j];
            }
        }
    }
    #pragma unroll
    for (int j = 0; j < 4; j++) {
        if ((unsigned)s[j] < NMAX && (unsigned)d[j] < NMAX) {
            int pos = atomicAdd(&g_cursor[d[j]], 1);
            g_col[pos] = s[j];
        }
    }
}

// ---------------- GEMM1: hp = (x @ W1) * dinv[row]  (100000x512 @ 512x16) ---
// v4: packed-over-k FFMA2. acc_f = (sum over even k, sum over odd k) for
// feature f. x pairs come free from LDS (v2.b64 of a float4); weights are
// staged pre-interleaved Wi[kp][f] = (W[2k][f], W[2k+1][f]). No mov.b64 dup.
__global__ __launch_bounds__(256) void k_gemm1(const float* __restrict__ x,
                                               const float* __restrict__ W1,
                                               int n) {
    __shared__ __align__(16) float Xs[256][36];        // 36KB; stride 144B (16B-aligned)
    __shared__ __align__(16) unsigned long long Wi[16 * 16];  // [kp][f] packed pairs, 2KB
    const int tid = threadIdx.x;
    const int row0 = blockIdx.x * 256;
    const int r = tid >> 1;        // 0..127
    const int h = tid & 1;         // output half: 8 features each
    const int rA = r, rB = r + 128;

    unsigned long long accA[8], accB[8];
    #pragma unroll
    for (int f = 0; f < 8; f++) { accA[f] = 0ull; accB[f] = 0ull; }

    const unsigned int xs_base = (unsigned int)__cvta_generic_to_shared(&Xs[0][0]);
    const unsigned int xa_base = xs_base + (unsigned int)(rA * 144);
    const unsigned int xb_base = xs_base + (unsigned int)(rB * 144);
    const unsigned int wi_base =
        (unsigned int)__cvta_generic_to_shared(&Wi[0]) + (unsigned int)(h * 64);

    const int kpl = tid >> 4;      // 0..15: k-pair slot this thread stages
    const int fl  = tid & 15;      // feature this thread stages

    for (int k0 = 0; k0 < F_IN; k0 += 32) {
        // stage X tile: 256 rows x 32 k = 2048 float4, 8 per thread
        #pragma unroll
        for (int j = 0; j < 8; j++) {
            int lin = tid + 256 * j;            // 0..2047
            int rr = lin >> 3;                  // 0..255
            int cc = (lin & 7) << 2;            // 0,4,...,28
            int grow = row0 + rr;
            float4 v = make_float4(0.f, 0.f, 0.f, 0.f);
            if (grow < n)
                v = *reinterpret_cast<const float4*>(&x[(long long)grow * F_IN + k0 + cc]);
            *reinterpret_cast<float4*>(&Xs[rr][cc]) = v;
        }
        // stage interleaved W chunk: Wi[kp][f] = (W[k0+2kp][f], W[k0+2kp+1][f])
        {
            float w0 = W1[(k0 + 2 * kpl) * F_MID + fl];
            float w1 = W1[(k0 + 2 * kpl + 1) * F_MID + fl];
            unsigned long long packed;
            asm("mov.b64 %0, {%1, %2};" : "=l"(packed) : "f"(w0), "f"(w1));
            Wi[kpl * 16 + fl] = packed;
        }
        __syncthreads();

        #pragma unroll
        for (int kk = 0; kk < 32; kk += 4) {
            unsigned long long xa01, xa23, xb01, xb23;
            asm("ld.shared.v2.b64 {%0, %1}, [%2];"
                : "=l"(xa01), "=l"(xa23) : "r"(xa_base + (unsigned)(kk * 4)));
            asm("ld.shared.v2.b64 {%0, %1}, [%2];"
                : "=l"(xb01), "=l"(xb23) : "r"(xb_base + (unsigned)(kk * 4)));
            #pragma unroll
            for (int p = 0; p < 2; p++) {
                unsigned long long xA = p ? xa23 : xa01;
                unsigned long long xB = p ? xb23 : xb01;
                unsigned int wa = wi_base + (unsigned)(((kk >> 1) + p) * 128);
                unsigned long long w0, w1, w2, w3, w4, w5, w6, w7;
                asm("ld.shared.v2.b64 {%0, %1}, [%2];" : "=l"(w0), "=l"(w1) : "r"(wa));
                asm("ld.shared.v2.b64 {%0, %1}, [%2];" : "=l"(w2), "=l"(w3) : "r"(wa + 16));
                asm("ld.shared.v2.b64 {%0, %1}, [%2];" : "=l"(w4), "=l"(w5) : "r"(wa + 32));
                asm("ld.shared.v2.b64 {%0, %1}, [%2];" : "=l"(w6), "=l"(w7) : "r"(wa + 48));
                asm("fma.rn.f32x2 %0, %1, %2, %0;" : "+l"(accA[0]) : "l"(xA), "l"(w0));
                asm("fma.rn.f32x2 %0, %1, %2, %0;" : "+l"(accA[1]) : "l"(xA), "l"(w1));
                asm("fma.rn.f32x2 %0, %1, %2, %0;" : "+l"(accA[2]) : "l"(xA), "l"(w2));
                asm("fma.rn.f32x2 %0, %1, %2, %0;" : "+l"(accA[3]) : "l"(xA), "l"(w3));
                asm("fma.rn.f32x2 %0, %1, %2, %0;" : "+l"(accA[4]) : "l"(xA), "l"(w4));
                asm("fma.rn.f32x2 %0, %1, %2, %0;" : "+l"(accA[5]) : "l"(xA), "l"(w5));
                asm("fma.rn.f32x2 %0, %1, %2, %0;" : "+l"(accA[6]) : "l"(xA), "l"(w6));
                asm("fma.rn.f32x2 %0, %1, %2, %0;" : "+l"(accA[7]) : "l"(xA), "l"(w7));
                asm("fma.rn.f32x2 %0, %1, %2, %0;" : "+l"(accB[0]) : "l"(xB), "l"(w0));
                asm("fma.rn.f32x2 %0, %1, %2, %0;" : "+l"(accB[1]) : "l"(xB), "l"(w1));
                asm("fma.rn.f32x2 %0, %1, %2, %0;" : "+l"(accB[2]) : "l"(xB), "l"(w2));
                asm("fma.rn.f32x2 %0, %1, %2, %0;" : "+l"(accB[3]) : "l"(xB), "l"(w3));
                asm("fma.rn.f32x2 %0, %1, %2, %0;" : "+l"(accB[4]) : "l"(xB), "l"(w4));
                asm("fma.rn.f32x2 %0, %1, %2, %0;" : "+l"(accB[5]) : "l"(xB), "l"(w5));
                asm("fma.rn.f32x2 %0, %1, %2, %0;" : "+l"(accB[6]) : "l"(xB), "l"(w6));
                asm("fma.rn.f32x2 %0, %1, %2, %0;" : "+l"(accB[7]) : "l"(xB), "l"(w7));
            }
        }
        __syncthreads();
    }

    #pragma unroll
    for (int rowSel = 0; rowSel < 2; rowSel++) {
        int grow = row0 + (rowSel ? rB : rA);
        if (grow < n) {
            const unsigned long long* acc = rowSel ? accB : accA;
            float dv = g_dinv[grow];
            float o[8];
            #pragma unroll
            for (int f = 0; f < 8; f++) {
                float e, od;
                asm("mov.b64 {%0, %1}, %2;" : "=f"(e), "=f"(od) : "l"(acc[f]));
                o[f] = (e + od) * dv;
            }
            float4* dst = reinterpret_cast<float4*>(&g_hp[(long long)grow * F_MID + h * 8]);
            dst[0] = make_float4(o[0], o[1], o[2], o[3]);
            dst[1] = make_float4(o[4], o[5], o[6], o[7]);
        }
    }
}

// ---------------- layer-1 aggregation: warp per node ------------------------
// h1p = relu(dinv*S + b1) * dinv    (hp -> h1p)
__global__ __launch_bounds__(256) void k_agg1(const float* __restrict__ bias, int n) {
    const int warp = (blockIdx.x * blockDim.x + threadIdx.x) >> 5;
    const int lane = threadIdx.x & 31;
    if (warp >= n) return;
    const int v = warp;
    const int g = lane >> 2;   // edge slot 0..7
    const int c = lane & 3;    // float4 index within 16 features

    const int base = g_rowptr[v];
    const int end  = g_rowptr[v + 1];

    float4 acc = make_float4(0.f, 0.f, 0.f, 0.f);
    #pragma unroll 2
    for (int i = base + g; i < end; i += 8) {
        int s = __ldg(&g_col[i]);
        float4 m = *reinterpret_cast<const float4*>(&g_hp[(long long)s * F_MID + c * 4]);
        acc.x += m.x; acc.y += m.y; acc.z += m.z; acc.w += m.w;
    }
    #pragma unroll
    for (int d = 4; d < 32; d <<= 1) {
        acc.x += __shfl_xor_sync(0xffffffffu, acc.x, d);
        acc.y += __shfl_xor_sync(0xffffffffu, acc.y, d);
        acc.z += __shfl_xor_sync(0xffffffffu, acc.z, d);
        acc.w += __shfl_xor_sync(0xffffffffu, acc.w, d);
    }
    if (lane < 4) {
        float4 self = *reinterpret_cast<const float4*>(&g_hp[(long long)v * F_MID + lane * 4]);
        acc.x += self.x; acc.y += self.y; acc.z += self.z; acc.w += self.w;
        float dv = g_dinv[v];
        float4 bb = *reinterpret_cast<const float4*>(&bias[lane * 4]);
        float4 o;
        o.x = fmaxf(acc.x * dv + bb.x, 0.f) * dv;
        o.y = fmaxf(acc.y * dv + bb.y, 0.f) * dv;
        o.z = fmaxf(acc.z * dv + bb.z, 0.f) * dv;
        o.w = fmaxf(acc.w * dv + bb.w, 0.f) * dv;
        *reinterpret_cast<float4*>(&g_h1p[(long long)v * F_MID + lane * 4]) = o;
    }
}

// ---------------- layer-2 aggregation FUSED with output GEMM + log_softmax --
// s2 = dinv * (sum_{src} h1p[src] + h1p[v]); out = log_softmax(s2 @ W2 + b2)
__global__ __launch_bounds__(256) void k_agg2_out(const float* __restrict__ W2,
                                                 const float* __restrict__ b2,
                                                 float* __restrict__ out, int n) {
    __shared__ float W2s[F_MID * F_OUT];  // 1024 floats
    {
        int tid = threadIdx.x;
        for (int i = tid; i < F_MID * F_OUT; i += 256) W2s[i] = W2[i];
    }
    __syncthreads();

    const int warp = (blockIdx.x * blockDim.x + threadIdx.x) >> 5;
    const int lane = threadIdx.x & 31;
    if (warp >= n) return;
    const int v = warp;
    const int g = lane >> 2;
    const int c = lane & 3;

    const int base = g_rowptr[v];
    const int end  = g_rowptr[v + 1];

    float4 acc = make_float4(0.f, 0.f, 0.f, 0.f);
    #pragma unroll 2
    for (int i = base + g; i < end; i += 8) {
        int s = __ldg(&g_col[i]);
        float4 m = *reinterpret_cast<const float4*>(&g_h1p[(long long)s * F_MID + c * 4]);
        acc.x += m.x; acc.y += m.y; acc.z += m.z; acc.w += m.w;
    }
    #pragma unroll
    for (int d = 4; d < 32; d <<= 1) {
        acc.x += __shfl_xor_sync(0xffffffffu, acc.x, d);
        acc.y += __shfl_xor_sync(0xffffffffu, acc.y, d);
        acc.z += __shfl_xor_sync(0xffffffffu, acc.z, d);
        acc.w += __shfl_xor_sync(0xffffffffu, acc.w, d);
    }
    if (lane < 4) {  // finalize s2 in lanes 0..3 (lane j holds feats 4j..4j+3)
        float4 self = *reinterpret_cast<const float4*>(&g_h1p[(long long)v * F_MID + lane * 4]);
        float dv = g_dinv[v];
        acc.x = (acc.x + self.x) * dv;
        acc.y = (acc.y + self.y) * dv;
        acc.z = (acc.z + self.z) * dv;
        acc.w = (acc.w + self.w) * dv;
    }
    // broadcast the 16 s2 values to all lanes
    float s2[F_MID];
    #pragma unroll
    for (int j = 0; j < 4; j++) {
        s2[4 * j + 0] = __shfl_sync(0xffffffffu, acc.x, j);
        s2[4 * j + 1] = __shfl_sync(0xffffffffu, acc.y, j);
        s2[4 * j + 2] = __shfl_sync(0xffffffffu, acc.z, j);
        s2[4 * j + 3] = __shfl_sync(0xffffffffu, acc.w, j);
    }
    // output GEMM: each lane computes feats (lane) and (lane+32)
    float a = b2[lane];
    float b = b2[lane + 32];
    #pragma unroll
    for (int f = 0; f < F_MID; f++) {
        a = fmaf(s2[f], W2s[f * F_OUT + lane], a);
        b = fmaf(s2[f], W2s[f * F_OUT + lane + 32], b);
    }
    float M = fmaxf(a, b);
    #pragma unroll
    for (int d = 16; d > 0; d >>= 1) M = fmaxf(M, __shfl_xor_sync(0xffffffffu, M, d));
    float sum = expf(a - M) + expf(b - M);
    #pragma unroll
    for (int d = 16; d > 0; d >>= 1) sum += __shfl_xor_sync(0xffffffffu, sum, d);
    float lz = M + logf(sum);
    out[(long long)v * F_OUT + lane]      = a - lz;
    out[(long long)v * F_OUT + lane + 32] = b - lz;
}

// ---------------- launch ----------------------------------------------------
extern "C" void kernel_launch(void* const* d_in, const int* in_sizes, int n_in,
                              void* d_out, int out_size) {
    const float* x  = (const float*)d_in[0];
    const void*  ei = d_in[1];
    const float* W1 = (const float*)d_in[2];
    const float* b1 = (const float*)d_in[3];
    const float* W2 = (const float*)d_in[4];
    const float* b2 = (const float*)d_in[5];
    float*       out = (float*)d_out;

    const int n = in_sizes[0] / F_IN;          // 100000
    const int E = in_sizes[1] / 2;             // 3200000

    const int B = 256;
    const int nodeGrid  = (n + B - 1) / B;
    const int quadGrid  = (E / 4 + B - 1) / B; // 4 edges per thread
    const int tiles     = (n + 1023) / 1024;
    const int warpGrid  = (n + 7) / 8;         // 8 warps per 256-thread block

    k_init_detect<<<nodeGrid, B>>>((const long long*)ei, n);
    k_count<<<quadGrid, B>>>(ei, E);
    k_scanAll<<<tiles, 1024>>>(n);
    k_fill<<<quadGrid, B>>>(ei, E);              // launch idx 3 -> profiled
    k_gemm1<<<(n + 255) / 256, B>>>(x, W1, n);
    k_agg1<<<warpGrid, B>>>(b1, n);
    k_agg2_out<<<warpGrid, B>>>(W2, b2, out, n);
}

// round 11
// speedup vs baseline: 1.3282x; 1.3282x over previous
#include <cuda_runtime.h>
#include <cuda_bf16.h>
#include <math.h>

// ---------------- problem-size constants (fixed per dataset) ----------------
#define NMAX 100000
#define EMAX 3200000
#define F_IN 512
#define F_MID 16
#define F_OUT 64

// ---------------- scratch (static device allocations; no cudaMalloc) -------
__device__ int   g_is64;               // edge_index dtype flag (1 = int64)
__device__ int   g_cnt[NMAX];          // in-degree (excl self loop)
__device__ float g_dinv[NMAX];         // rsqrt(deg+1)
__device__ int   g_tile_pub[128];      // lookback: tile aggregate + 1 (0 = not ready)
__device__ int   g_rowptr[NMAX + 1];
__device__ int   g_cursor[NMAX];
__device__ int   g_col[EMAX];          // CSR source indices grouped by dst
__device__ __align__(16) float g_hp[NMAX * F_MID];    // x@W1, then *dinv after k_scale
__device__ __align__(16) float g_h1p[NMAX * F_MID];   // relu(layer1)*dinv

// ---------------- init + dtype detection -------------------------------------
// JAX default config demotes int64 -> int32; detect which layout we actually
// got: if the first 16 int64 reads are all valid node ids, it's real int64.
__global__ void k_init_detect(const long long* __restrict__ ei, int n) {
    int i = blockIdx.x * blockDim.x + threadIdx.x;
    if (i < n) g_cnt[i] = 0;
    if (i < 128) g_tile_pub[i] = 0;
    if (i == 0) {
        bool ok64 = true;
        #pragma unroll
        for (int t = 0; t < 16; t++) {
            long long v = ei[t];
            if (v < 0 || v >= NMAX) ok64 = false;
        }
        g_is64 = ok64 ? 1 : 0;
    }
}

// ---------------- degree count (8 edges / thread for atomic MLP) ------------
__global__ void k_count(const void* __restrict__ ei, int E) {
    long long e8 = (long long)(blockIdx.x * blockDim.x + threadIdx.x) * 8;
    if (e8 >= E) return;
    int d[8];
    if (e8 + 7 < E) {
        if (g_is64) {
            const longlong2* p = (const longlong2*)((const long long*)ei + E + e8);
            #pragma unroll
            for (int j = 0; j < 4; j++) {
                longlong2 v = p[j];
                d[2 * j] = (int)v.x; d[2 * j + 1] = (int)v.y;
            }
        } else {
            const int4* p = (const int4*)((const int*)ei + E + e8);
            int4 v0 = p[0], v1 = p[1];
            d[0] = v0.x; d[1] = v0.y; d[2] = v0.z; d[3] = v0.w;
            d[4] = v1.x; d[5] = v1.y; d[6] = v1.z; d[7] = v1.w;
        }
    } else {
        #pragma unroll
        for (int j = 0; j < 8; j++) {
            d[j] = -1;
            if (e8 + j < E)
                d[j] = g_is64 ? (int)((const long long*)ei)[E + e8 + j]
                              : ((const int*)ei)[E + e8 + j];
        }
    }
    #pragma unroll
    for (int j = 0; j < 8; j++)
        if ((unsigned)d[j] < NMAX) atomicAdd(&g_cnt[d[j]], 1);
}

// ---------------- single-pass scan with decoupled lookback ------------------
// Publication (total+1) happens BEFORE the lookback spin, so any scheduled-
// later block only needs earlier blocks to have STARTED; concurrent gemm
// blocks retire continuously so scheduling always progresses. No deadlock.
__global__ void k_scanAll(int n) {
    __shared__ int wsum[32];
    __shared__ int sprefix;
    const int lane = threadIdx.x & 31;
    const int wid  = threadIdx.x >> 5;
    const int b    = blockIdx.x;
    int idx = b * 1024 + threadIdx.x;
    int v = (idx < n) ? g_cnt[idx] : 0;
    if (idx < n) g_dinv[idx] = rsqrtf((float)(v + 1));  // +1 self loop

    int s = v;
    #pragma unroll
    for (int d = 1; d < 32; d <<= 1) {
        int t = __shfl_up_sync(0xffffffffu, s, d);
        if (lane >= d) s += t;
    }
    if (lane == 31) wsum[wid] = s;
    __syncthreads();
    if (wid == 0) {
        int w = wsum[lane];
        #pragma unroll
        for (int d = 1; d < 32; d <<= 1) {
            int t = __shfl_up_sync(0xffffffffu, w, d);
            if (lane >= d) w += t;
        }
        wsum[lane] = w;  // inclusive over warp sums
    }
    __syncthreads();
    if (wid > 0) s += wsum[wid - 1];
    // s = inclusive prefix within tile; tile total = wsum[31]

    if (threadIdx.x == 0) {
        ((volatile int*)g_tile_pub)[b] = wsum[31] + 1;  // publish aggregate
    }
    // lookback: warp 0 sums aggregates of tiles 0..b-1
    if (wid == 0) {
        int pre = 0;
        for (int j = lane; j < b; j += 32) {
            int p;
            do { p = ((volatile int*)g_tile_pub)[j]; } while (p == 0);
            pre += p - 1;
        }
        #pragma unroll
        for (int d = 16; d > 0; d >>= 1)
            pre += __shfl_xor_sync(0xffffffffu, pre, d);
        if (lane == 0) sprefix = pre;
    }
    __syncthreads();
    int excl = sprefix + s - v;
    if (idx < n) {
        g_rowptr[idx] = excl;
        g_cursor[idx] = excl;
        if (idx == n - 1) g_rowptr[n] = sprefix + s;
    }
}

// ---------------- CSR bucket fill (8 edges / thread) -------------------------
__global__ void k_fill(const void* __restrict__ ei, int E) {
    long long e8 = (long long)(blockIdx.x * blockDim.x + threadIdx.x) * 8;
    if (e8 >= E) return;
    int s[8], d[8];
    if (e8 + 7 < E) {
        if (g_is64) {
            const longlong2* ps = (const longlong2*)((const long long*)ei + e8);
            const longlong2* pd = (const longlong2*)((const long long*)ei + E + e8);
            #pragma unroll
            for (int j = 0; j < 4; j++) {
                longlong2 a = ps[j], b = pd[j];
                s[2 * j] = (int)a.x; s[2 * j + 1] = (int)a.y;
                d[2 * j] = (int)b.x; d[2 * j + 1] = (int)b.y;
            }
        } else {
            const int4* ps = (const int4*)((const int*)ei + e8);
            const int4* pd = (const int4*)((const int*)ei + E + e8);
            int4 a0 = ps[0], a1 = ps[1], b0 = pd[0], b1 = pd[1];
            s[0] = a0.x; s[1] = a0.y; s[2] = a0.z; s[3] = a0.w;
            s[4] = a1.x; s[5] = a1.y; s[6] = a1.z; s[7] = a1.w;
            d[0] = b0.x; d[1] = b0.y; d[2] = b0.z; d[3] = b0.w;
            d[4] = b1.x; d[5] = b1.y; d[6] = b1.z; d[7] = b1.w;
        }
    } else {
        #pragma unroll
        for (int j = 0; j < 8; j++) {
            s[j] = -1; d[j] = -1;
            if (e8 + j < E) {
                if (g_is64) {
                    s[j] = (int)((const long long*)ei)[e8 + j];
                    d[j] = (int)((const long long*)ei)[E + e8 + j];
                } else {
                    s[j] = ((const int*)ei)[e8 + j];
                    d[j] = ((const int*)ei)[E + e8 + j];
                }
            }
        }
    }
    #pragma unroll
    for (int j = 0; j < 8; j++) {
        if ((unsigned)s[j] < NMAX && (unsigned)d[j] < NMAX) {
            int pos = atomicAdd(&g_cursor[d[j]], 1);
            g_col[pos] = s[j];
        }
    }
}

// ---------------- GEMM1 (v3, measured 59.5us): g_hp = x @ W1 ----------------
// 2 rows/thread (256-row tile); x from smem as float4; f32x2 packed FMAs.
// dinv is NOT folded here (applied by k_scale after the stream join) so this
// kernel is fully independent of the CSR-build chain and can overlap it.
__global__ __launch_bounds__(256) void k_gemm1(const float* __restrict__ x,
                                               const float* __restrict__ W1,
                                               int n) {
    __shared__ __align__(16) float Xs[256][36];   // 36KB; pad 36 keeps 16B align
    __shared__ __align__(16) float Ws[32][16];    // 2KB K-chunk of W1
    const int tid = threadIdx.x;
    const int row0 = blockIdx.x * 256;
    const int r = tid >> 1;        // 0..127
    const int h = tid & 1;         // output half: 8 features each
    const int rA = r, rB = r + 128;

    unsigned long long a0 = 0ull, a1 = 0ull, a2 = 0ull, a3 = 0ull;  // row A
    unsigned long long b0 = 0ull, b1 = 0ull, b2 = 0ull, b3 = 0ull;  // row B

    unsigned int ws_base =
        (unsigned int)__cvta_generic_to_shared(&Ws[0][0]) + (unsigned int)(h * 32);

    for (int k0 = 0; k0 < F_IN; k0 += 32) {
        // stage X tile: 256 rows x 32 k = 2048 float4, 8 per thread
        #pragma unroll
        for (int j = 0; j < 8; j++) {
            int lin = tid + 256 * j;            // 0..2047
            int rr = lin >> 3;                  // 0..255
            int cc = (lin & 7) << 2;            // 0,4,...,28
            int grow = row0 + rr;
            float4 v = make_float4(0.f, 0.f, 0.f, 0.f);
            if (grow < n)
                v = *reinterpret_cast<const float4*>(&x[(long long)grow * F_IN + k0 + cc]);
            *reinterpret_cast<float4*>(&Xs[rr][cc]) = v;
        }
        // stage W chunk: 32x16 = 512 floats = 128 float4
        if (tid < 128)
            reinterpret_cast<float4*>(Ws)[tid] =
                reinterpret_cast<const float4*>(W1 + k0 * F_MID)[tid];
        __syncthreads();

        #pragma unroll
        for (int kk = 0; kk < 32; kk += 4) {
            float4 xa = *reinterpret_cast<const float4*>(&Xs[rA][kk]);
            float4 xb = *reinterpret_cast<const float4*>(&Xs[rB][kk]);
            const float xav[4] = {xa.x, xa.y, xa.z, xa.w};
            const float xbv[4] = {xb.x, xb.y, xb.z, xb.w};
            #pragma unroll
            for (int j = 0; j < 4; j++) {
                unsigned long long xxa, xxb, w01, w23, w45, w67;
                asm("mov.b64 %0, {%1, %1};" : "=l"(xxa) : "f"(xav[j]));
                asm("mov.b64 %0, {%1, %1};" : "=l"(xxb) : "f"(xbv[j]));
                unsigned int adr = ws_base + (unsigned int)((kk + j) * 64);
                asm("ld.shared.v2.b64 {%0, %1}, [%2];"
                    : "=l"(w01), "=l"(w23) : "r"(adr));
                asm("ld.shared.v2.b64 {%0, %1}, [%2];"
                    : "=l"(w45), "=l"(w67) : "r"(adr + 16));
                asm("fma.rn.f32x2 %0, %1, %2, %0;" : "+l"(a0) : "l"(xxa), "l"(w01));
                asm("fma.rn.f32x2 %0, %1, %2, %0;" : "+l"(a1) : "l"(xxa), "l"(w23));
                asm("fma.rn.f32x2 %0, %1, %2, %0;" : "+l"(a2) : "l"(xxa), "l"(w45));
                asm("fma.rn.f32x2 %0, %1, %2, %0;" : "+l"(a3) : "l"(xxa), "l"(w67));
                asm("fma.rn.f32x2 %0, %1, %2, %0;" : "+l"(b0) : "l"(xxb), "l"(w01));
                asm("fma.rn.f32x2 %0, %1, %2, %0;" : "+l"(b1) : "l"(xxb), "l"(w23));
                asm("fma.rn.f32x2 %0, %1, %2, %0;" : "+l"(b2) : "l"(xxb), "l"(w45));
                asm("fma.rn.f32x2 %0, %1, %2, %0;" : "+l"(b3) : "l"(xxb), "l"(w67));
            }
        }
        __syncthreads();
    }

    #pragma unroll
    for (int rowSel = 0; rowSel < 2; rowSel++) {
        int grow = row0 + (rowSel ? rB : rA);
        if (grow < n) {
            unsigned long long c0 = rowSel ? b0 : a0;
            unsigned long long c1 = rowSel ? b1 : a1;
            unsigned long long c2 = rowSel ? b2 : a2;
            unsigned long long c3 = rowSel ? b3 : a3;
            float f0, f1, f2, f3, f4, f5, f6, f7;
            asm("mov.b64 {%0, %1}, %2;" : "=f"(f0), "=f"(f1) : "l"(c0));
            asm("mov.b64 {%0, %1}, %2;" : "=f"(f2), "=f"(f3) : "l"(c1));
            asm("mov.b64 {%0, %1}, %2;" : "=f"(f4), "=f"(f5) : "l"(c2));
            asm("mov.b64 {%0, %1}, %2;" : "=f"(f6), "=f"(f7) : "l"(c3));
            float4* dst = reinterpret_cast<float4*>(&g_hp[(long long)grow * F_MID + h * 8]);
            dst[0] = make_float4(f0, f1, f2, f3);
            dst[1] = make_float4(f4, f5, f6, f7);
        }
    }
}

// ---------------- apply dinv to g_hp (after join) ---------------------------
__global__ void k_scale(int n) {
    int idx = blockIdx.x * blockDim.x + threadIdx.x;  // one float4 per thread
    if (idx >= n * 4) return;
    float dv = g_dinv[idx >> 2];
    float4* p = reinterpret_cast<float4*>(g_hp) + idx;
    float4 v = *p;
    v.x *= dv; v.y *= dv; v.z *= dv; v.w *= dv;
    *p = v;
}

// ---------------- layer-1 aggregation: warp per node ------------------------
// h1p = relu(dinv*S + b1) * dinv    (hp -> h1p)
__global__ __launch_bounds__(256) void k_agg1(const float* __restrict__ bias, int n) {
    const int warp = (blockIdx.x * blockDim.x + threadIdx.x) >> 5;
    const int lane = threadIdx.x & 31;
    if (warp >= n) return;
    const int v = warp;
    const int g = lane >> 2;   // edge slot 0..7
    const int c = lane & 3;    // float4 index within 16 features

    const int base = g_rowptr[v];
    const int end  = g_rowptr[v + 1];

    float4 acc = make_float4(0.f, 0.f, 0.f, 0.f);
    #pragma unroll 2
    for (int i = base + g; i < end; i += 8) {
        int s = __ldg(&g_col[i]);
        float4 m = *reinterpret_cast<const float4*>(&g_hp[(long long)s * F_MID + c * 4]);
        acc.x += m.x; acc.y += m.y; acc.z += m.z; acc.w += m.w;
    }
    #pragma unroll
    for (int d = 4; d < 32; d <<= 1) {
        acc.x += __shfl_xor_sync(0xffffffffu, acc.x, d);
        acc.y += __shfl_xor_sync(0xffffffffu, acc.y, d);
        acc.z += __shfl_xor_sync(0xffffffffu, acc.z, d);
        acc.w += __shfl_xor_sync(0xffffffffu, acc.w, d);
    }
    if (lane < 4) {
        float4 self = *reinterpret_cast<const float4*>(&g_hp[(long long)v * F_MID + lane * 4]);
        acc.x += self.x; acc.y += self.y; acc.z += self.z; acc.w += self.w;
        float dv = g_dinv[v];
        float4 bb = *reinterpret_cast<const float4*>(&bias[lane * 4]);
        float4 o;
        o.x = fmaxf(acc.x * dv + bb.x, 0.f) * dv;
        o.y = fmaxf(acc.y * dv + bb.y, 0.f) * dv;
        o.z = fmaxf(acc.z * dv + bb.z, 0.f) * dv;
        o.w = fmaxf(acc.w * dv + bb.w, 0.f) * dv;
        *reinterpret_cast<float4*>(&g_h1p[(long long)v * F_MID + lane * 4]) = o;
    }
}

// ---------------- layer-2 aggregation FUSED with output GEMM + log_softmax --
// s2 = dinv * (sum_{src} h1p[src] + h1p[v]); out = log_softmax(s2 @ W2 + b2)
__global__ __launch_bounds__(256) void k_agg2_out(const float* __restrict__ W2,
                                                 const float* __restrict__ b2,
                                                 float* __restrict__ out, int n) {
    __shared__ float W2s[F_MID * F_OUT];  // 1024 floats
    {
        int tid = threadIdx.x;
        for (int i = tid; i < F_MID * F_OUT; i += 256) W2s[i] = W2[i];
    }
    __syncthreads();

    const int warp = (blockIdx.x * blockDim.x + threadIdx.x) >> 5;
    const int lane = threadIdx.x & 31;
    if (warp >= n) return;
    const int v = warp;
    const int g = lane >> 2;
    const int c = lane & 3;

    const int base = g_rowptr[v];
    const int end  = g_rowptr[v + 1];

    float4 acc = make_float4(0.f, 0.f, 0.f, 0.f);
    #pragma unroll 2
    for (int i = base + g; i < end; i += 8) {
        int s = __ldg(&g_col[i]);
        float4 m = *reinterpret_cast<const float4*>(&g_h1p[(long long)s * F_MID + c * 4]);
        acc.x += m.x; acc.y += m.y; acc.z += m.z; acc.w += m.w;
    }
    #pragma unroll
    for (int d = 4; d < 32; d <<= 1) {
        acc.x += __shfl_xor_sync(0xffffffffu, acc.x, d);
        acc.y += __shfl_xor_sync(0xffffffffu, acc.y, d);
        acc.z += __shfl_xor_sync(0xffffffffu, acc.z, d);
        acc.w += __shfl_xor_sync(0xffffffffu, acc.w, d);
    }
    if (lane < 4) {  // finalize s2 in lanes 0..3 (lane j holds feats 4j..4j+3)
        float4 self = *reinterpret_cast<const float4*>(&g_h1p[(long long)v * F_MID + lane * 4]);
        float dv = g_dinv[v];
        acc.x = (acc.x + self.x) * dv;
        acc.y = (acc.y + self.y) * dv;
        acc.z = (acc.z + self.z) * dv;
        acc.w = (acc.w + self.w) * dv;
    }
    // broadcast the 16 s2 values to all lanes
    float s2[F_MID];
    #pragma unroll
    for (int j = 0; j < 4; j++) {
        s2[4 * j + 0] = __shfl_sync(0xffffffffu, acc.x, j);
        s2[4 * j + 1] = __shfl_sync(0xffffffffu, acc.y, j);
        s2[4 * j + 2] = __shfl_sync(0xffffffffu, acc.z, j);
        s2[4 * j + 3] = __shfl_sync(0xffffffffu, acc.w, j);
    }
    // output GEMM: each lane computes feats (lane) and (lane+32)
    float a = b2[lane];
    float b = b2[lane + 32];
    #pragma unroll
    for (int f = 0; f < F_MID; f++) {
        a = fmaf(s2[f], W2s[f * F_OUT + lane], a);
        b = fmaf(s2[f], W2s[f * F_OUT + lane + 32], b);
    }
    float M = fmaxf(a, b);
    #pragma unroll
    for (int d = 16; d > 0; d >>= 1) M = fmaxf(M, __shfl_xor_sync(0xffffffffu, M, d));
    float sum = expf(a - M) + expf(b - M);
    #pragma unroll
    for (int d = 16; d > 0; d >>= 1) sum += __shfl_xor_sync(0xffffffffu, sum, d);
    float lz = M + logf(sum);
    out[(long long)v * F_OUT + lane]      = a - lz;
    out[(long long)v * F_OUT + lane + 32] = b - lz;
}

// ---------------- launch (fork/join: gemm overlaps CSR build) ---------------
extern "C" void kernel_launch(void* const* d_in, const int* in_sizes, int n_in,
                              void* d_out, int out_size) {
    const float* x  = (const float*)d_in[0];
    const void*  ei = d_in[1];
    const float* W1 = (const float*)d_in[2];
    const float* b1 = (const float*)d_in[3];
    const float* W2 = (const float*)d_in[4];
    const float* b2 = (const float*)d_in[5];
    float*       out = (float*)d_out;

    const int n = in_sizes[0] / F_IN;          // 100000
    const int E = in_sizes[1] / 2;             // 3200000

    const int B = 256;
    const int nodeGrid  = (n + B - 1) / B;
    const int octGrid   = (int)(((long long)E / 8 + B) / B);  // 8 edges per thread
    const int tiles     = (n + 1023) / 1024;
    const int warpGrid  = (n + 7) / 8;         // 8 warps per 256-thread block
    const int scaleGrid = (n * 4 + B - 1) / B;

    // Persistent side stream + events. Created on the first (non-capturing)
    // correctness call; reused thereafter. Work launched is identical on
    // every call — this caches host handles only, never skips device work.
    static cudaStream_t s1 = nullptr;
    static cudaEvent_t evFork = nullptr, evJoin = nullptr;
    if (s1 == nullptr) {
        cudaStreamCreateWithFlags(&s1, cudaStreamNonBlocking);
        cudaEventCreateWithFlags(&evFork, cudaEventDisableTiming);
        cudaEventCreateWithFlags(&evJoin, cudaEventDisableTiming);
    }

    // Fork: gemm1 (independent of edges) runs on s1 while the CSR build
    // chain runs on the main stream.
    cudaEventRecord(evFork, 0);
    cudaStreamWaitEvent(s1, evFork, 0);
    k_gemm1<<<(n + 255) / 256, B, 0, s1>>>(x, W1, n);
    cudaEventRecord(evJoin, s1);

    k_init_detect<<<nodeGrid, B>>>((const long long*)ei, n);
    k_count<<<octGrid, B>>>(ei, E);
    k_scanAll<<<tiles, 1024>>>(n);
    k_fill<<<octGrid, B>>>(ei, E);

    // Join: everything below needs both gemm1 and the CSR build.
    cudaStreamWaitEvent(0, evJoin, 0);
    k_scale<<<scaleGrid, B>>>(n);
    k_agg1<<<warpGrid, B>>>(b1, n);
    k_agg2_out<<<warpGrid, B>>>(W2, b2, out, n);
}

// round 13
// speedup vs baseline: 1.3349x; 1.0050x over previous
#include <cuda_runtime.h>
#include <cuda_bf16.h>
#include <math.h>

// ---------------- problem-size constants (fixed per dataset) ----------------
#define NMAX 100000
#define EMAX 3200000
#define F_IN 512
#define F_MID 16
#define F_OUT 64

// ---------------- scratch (static device allocations; no cudaMalloc) -------
__device__ int   g_is64;               // edge_index dtype flag (1 = int64)
__device__ int   g_cnt[NMAX];          // in-degree (excl self loop)
__device__ float g_dinv[NMAX];         // rsqrt(deg+1)
__device__ int   g_tile_pub[128];      // lookback: tile aggregate + 1 (0 = not ready)
__device__ int   g_rowptr[NMAX + 1];
__device__ int   g_cursor[NMAX];
__device__ int   g_col[EMAX];          // CSR source indices grouped by dst
__device__ __align__(16) float g_hp[NMAX * F_MID];    // x@W1, then *dinv after k_scale
__device__ __align__(16) float g_h1p[NMAX * F_MID];   // relu(layer1)*dinv

// ---------------- init + dtype detection -------------------------------------
// JAX default config demotes int64 -> int32; detect which layout we actually
// got: if the first 16 int64 reads are all valid node ids, it's real int64.
__global__ void k_init_detect(const long long* __restrict__ ei, int n) {
    int i = blockIdx.x * blockDim.x + threadIdx.x;
    if (i < n) g_cnt[i] = 0;
    if (i < 128) g_tile_pub[i] = 0;
    if (i == 0) {
        bool ok64 = true;
        #pragma unroll
        for (int t = 0; t < 16; t++) {
            long long v = ei[t];
            if (v < 0 || v >= NMAX) ok64 = false;
        }
        g_is64 = ok64 ? 1 : 0;
    }
}

// ---------------- degree count (16 edges / thread for atomic MLP) -----------
__global__ void k_count(const void* __restrict__ ei, int E) {
    long long e0 = (long long)(blockIdx.x * blockDim.x + threadIdx.x) * 16;
    if (e0 >= E) return;
    int d[16];
    if (e0 + 15 < E) {
        if (g_is64) {
            const longlong2* p = (const longlong2*)((const long long*)ei + E + e0);
            #pragma unroll
            for (int j = 0; j < 8; j++) {
                longlong2 v = p[j];
                d[2 * j] = (int)v.x; d[2 * j + 1] = (int)v.y;
            }
        } else {
            const int4* p = (const int4*)((const int*)ei + E + e0);
            #pragma unroll
            for (int j = 0; j < 4; j++) {
                int4 v = p[j];
                d[4 * j] = v.x; d[4 * j + 1] = v.y; d[4 * j + 2] = v.z; d[4 * j + 3] = v.w;
            }
        }
    } else {
        #pragma unroll
        for (int j = 0; j < 16; j++) {
            d[j] = -1;
            if (e0 + j < E)
                d[j] = g_is64 ? (int)((const long long*)ei)[E + e0 + j]
                              : ((const int*)ei)[E + e0 + j];
        }
    }
    #pragma unroll
    for (int j = 0; j < 16; j++)
        if ((unsigned)d[j] < NMAX) atomicAdd(&g_cnt[d[j]], 1);
}

// ---------------- single-pass scan with decoupled lookback ------------------
// Publication (total+1) happens BEFORE the lookback spin, so any scheduled-
// later block only needs earlier blocks to have STARTED; concurrent gemm
// blocks retire continuously so scheduling always progresses. No deadlock.
__global__ void k_scanAll(int n) {
    __shared__ int wsum[32];
    __shared__ int sprefix;
    const int lane = threadIdx.x & 31;
    const int wid  = threadIdx.x >> 5;
    const int b    = blockIdx.x;
    int idx = b * 1024 + threadIdx.x;
    int v = (idx < n) ? g_cnt[idx] : 0;
    if (idx < n) g_dinv[idx] = rsqrtf((float)(v + 1));  // +1 self loop

    int s = v;
    #pragma unroll
    for (int d = 1; d < 32; d <<= 1) {
        int t = __shfl_up_sync(0xffffffffu, s, d);
        if (lane >= d) s += t;
    }
    if (lane == 31) wsum[wid] = s;
    __syncthreads();
    if (wid == 0) {
        int w = wsum[lane];
        #pragma unroll
        for (int d = 1; d < 32; d <<= 1) {
            int t = __shfl_up_sync(0xffffffffu, w, d);
            if (lane >= d) w += t;
        }
        wsum[lane] = w;  // inclusive over warp sums
    }
    __syncthreads();
    if (wid > 0) s += wsum[wid - 1];
    // s = inclusive prefix within tile; tile total = wsum[31]

    if (threadIdx.x == 0) {
        ((volatile int*)g_tile_pub)[b] = wsum[31] + 1;  // publish aggregate
    }
    // lookback: warp 0 sums aggregates of tiles 0..b-1
    if (wid == 0) {
        int pre = 0;
        for (int j = lane; j < b; j += 32) {
            int p;
            do { p = ((volatile int*)g_tile_pub)[j]; } while (p == 0);
            pre += p - 1;
        }
        #pragma unroll
        for (int d = 16; d > 0; d >>= 1)
            pre += __shfl_xor_sync(0xffffffffu, pre, d);
        if (lane == 0) sprefix = pre;
    }
    __syncthreads();
    int excl = sprefix + s - v;
    if (idx < n) {
        g_rowptr[idx] = excl;
        g_cursor[idx] = excl;
        if (idx == n - 1) g_rowptr[n] = sprefix + s;
    }
}

// ---------------- CSR bucket fill (16 edges / thread) ------------------------
__global__ void k_fill(const void* __restrict__ ei, int E) {
    long long e0 = (long long)(blockIdx.x * blockDim.x + threadIdx.x) * 16;
    if (e0 >= E) return;
    int s[16], d[16];
    if (e0 + 15 < E) {
        if (g_is64) {
            const longlong2* ps = (const longlong2*)((const long long*)ei + e0);
            const longlong2* pd = (const longlong2*)((const long long*)ei + E + e0);
            #pragma unroll
            for (int j = 0; j < 8; j++) {
                longlong2 a = ps[j], b = pd[j];
                s[2 * j] = (int)a.x; s[2 * j + 1] = (int)a.y;
                d[2 * j] = (int)b.x; d[2 * j + 1] = (int)b.y;
            }
        } else {
            const int4* ps = (const int4*)((const int*)ei + e0);
            const int4* pd = (const int4*)((const int*)ei + E + e0);
            #pragma unroll
            for (int j = 0; j < 4; j++) {
                int4 a = ps[j], b = pd[j];
                s[4 * j] = a.x; s[4 * j + 1] = a.y; s[4 * j + 2] = a.z; s[4 * j + 3] = a.w;
                d[4 * j] = b.x; d[4 * j + 1] = b.y; d[4 * j + 2] = b.z; d[4 * j + 3] = b.w;
            }
        }
    } else {
        #pragma unroll
        for (int j = 0; j < 16; j++) {
            s[j] = -1; d[j] = -1;
            if (e0 + j < E) {
                if (g_is64) {
                    s[j] = (int)((const long long*)ei)[e0 + j];
                    d[j] = (int)((const long long*)ei)[E + e0 + j];
                } else {
                    s[j] = ((const int*)ei)[e0 + j];
                    d[j] = ((const int*)ei)[E + e0 + j];
                }
            }
        }
    }
    #pragma unroll
    for (int j = 0; j < 16; j++) {
        if ((unsigned)s[j] < NMAX && (unsigned)d[j] < NMAX) {
            int pos = atomicAdd(&g_cursor[d[j]], 1);
            g_col[pos] = s[j];
        }
    }
}

// ---------------- GEMM1 (v3, measured 59.5us): g_hp = x @ W1 ----------------
// 2 rows/thread (256-row tile); x from smem as float4; f32x2 packed FMAs.
// dinv is NOT folded here (applied by k_scale on the side stream) so this
// kernel is fully independent of the CSR-build chain and can overlap it.
__global__ __launch_bounds__(256) void k_gemm1(const float* __restrict__ x,
                                               const float* __restrict__ W1,
                                               int n) {
    __shared__ __align__(16) float Xs[256][36];   // 36KB; pad 36 keeps 16B align
    __shared__ __align__(16) float Ws[32][16];    // 2KB K-chunk of W1
    const int tid = threadIdx.x;
    const int row0 = blockIdx.x * 256;
    const int r = tid >> 1;        // 0..127
    const int h = tid & 1;         // output half: 8 features each
    const int rA = r, rB = r + 128;

    unsigned long long a0 = 0ull, a1 = 0ull, a2 = 0ull, a3 = 0ull;  // row A
    unsigned long long b0 = 0ull, b1 = 0ull, b2 = 0ull, b3 = 0ull;  // row B

    unsigned int ws_base =
        (unsigned int)__cvta_generic_to_shared(&Ws[0][0]) + (unsigned int)(h * 32);

    for (int k0 = 0; k0 < F_IN; k0 += 32) {
        // stage X tile: 256 rows x 32 k = 2048 float4, 8 per thread
        #pragma unroll
        for (int j = 0; j < 8; j++) {
            int lin = tid + 256 * j;            // 0..2047
            int rr = lin >> 3;                  // 0..255
            int cc = (lin & 7) << 2;            // 0,4,...,28
            int grow = row0 + rr;
            float4 v = make_float4(0.f, 0.f, 0.f, 0.f);
            if (grow < n)
                v = *reinterpret_cast<const float4*>(&x[(long long)grow * F_IN + k0 + cc]);
            *reinterpret_cast<float4*>(&Xs[rr][cc]) = v;
        }
        // stage W chunk: 32x16 = 512 floats = 128 float4
        if (tid < 128)
            reinterpret_cast<float4*>(Ws)[tid] =
                reinterpret_cast<const float4*>(W1 + k0 * F_MID)[tid];
        __syncthreads();

        #pragma unroll
        for (int kk = 0; kk < 32; kk += 4) {
            float4 xa = *reinterpret_cast<const float4*>(&Xs[rA][kk]);
            float4 xb = *reinterpret_cast<const float4*>(&Xs[rB][kk]);
            const float xav[4] = {xa.x, xa.y, xa.z, xa.w};
            const float xbv[4] = {xb.x, xb.y, xb.z, xb.w};
            #pragma unroll
            for (int j = 0; j < 4; j++) {
                unsigned long long xxa, xxb, w01, w23, w45, w67;
                asm("mov.b64 %0, {%1, %1};" : "=l"(xxa) : "f"(xav[j]));
                asm("mov.b64 %0, {%1, %1};" : "=l"(xxb) : "f"(xbv[j]));
                unsigned int adr = ws_base + (unsigned int)((kk + j) * 64);
                asm("ld.shared.v2.b64 {%0, %1}, [%2];"
                    : "=l"(w01), "=l"(w23) : "r"(adr));
                asm("ld.shared.v2.b64 {%0, %1}, [%2];"
                    : "=l"(w45), "=l"(w67) : "r"(adr + 16));
                asm("fma.rn.f32x2 %0, %1, %2, %0;" : "+l"(a0) : "l"(xxa), "l"(w01));
                asm("fma.rn.f32x2 %0, %1, %2, %0;" : "+l"(a1) : "l"(xxa), "l"(w23));
                asm("fma.rn.f32x2 %0, %1, %2, %0;" : "+l"(a2) : "l"(xxa), "l"(w45));
                asm("fma.rn.f32x2 %0, %1, %2, %0;" : "+l"(a3) : "l"(xxa), "l"(w67));
                asm("fma.rn.f32x2 %0, %1, %2, %0;" : "+l"(b0) : "l"(xxb), "l"(w01));
                asm("fma.rn.f32x2 %0, %1, %2, %0;" : "+l"(b1) : "l"(xxb), "l"(w23));
                asm("fma.rn.f32x2 %0, %1, %2, %0;" : "+l"(b2) : "l"(xxb), "l"(w45));
                asm("fma.rn.f32x2 %0, %1, %2, %0;" : "+l"(b3) : "l"(xxb), "l"(w67));
            }
        }
        __syncthreads();
    }

    #pragma unroll
    for (int rowSel = 0; rowSel < 2; rowSel++) {
        int grow = row0 + (rowSel ? rB : rA);
        if (grow < n) {
            unsigned long long c0 = rowSel ? b0 : a0;
            unsigned long long c1 = rowSel ? b1 : a1;
            unsigned long long c2 = rowSel ? b2 : a2;
            unsigned long long c3 = rowSel ? b3 : a3;
            float f0, f1, f2, f3, f4, f5, f6, f7;
            asm("mov.b64 {%0, %1}, %2;" : "=f"(f0), "=f"(f1) : "l"(c0));
            asm("mov.b64 {%0, %1}, %2;" : "=f"(f2), "=f"(f3) : "l"(c1));
            asm("mov.b64 {%0, %1}, %2;" : "=f"(f4), "=f"(f5) : "l"(c2));
            asm("mov.b64 {%0, %1}, %2;" : "=f"(f6), "=f"(f7) : "l"(c3));
            float4* dst = reinterpret_cast<float4*>(&g_hp[(long long)grow * F_MID + h * 8]);
            dst[0] = make_float4(f0, f1, f2, f3);
            dst[1] = make_float4(f4, f5, f6, f7);
        }
    }
}

// ---------------- apply dinv to g_hp (side stream, overlaps k_fill) ---------
__global__ void k_scale(int n) {
    int idx = blockIdx.x * blockDim.x + threadIdx.x;  // one float4 per thread
    if (idx >= n * 4) return;
    float dv = g_dinv[idx >> 2];
    float4* p = reinterpret_cast<float4*>(g_hp) + idx;
    float4 v = *p;
    v.x *= dv; v.y *= dv; v.z *= dv; v.w *= dv;
    *p = v;
}

// ---------------- layer-1 aggregation: warp per node ------------------------
// h1p = relu(dinv*S + b1) * dinv    (hp -> h1p)
__global__ __launch_bounds__(256) void k_agg1(const float* __restrict__ bias, int n) {
    const int warp = (blockIdx.x * blockDim.x + threadIdx.x) >> 5;
    const int lane = threadIdx.x & 31;
    if (warp >= n) return;
    const int v = warp;
    const int g = lane >> 2;   // edge slot 0..7
    const int c = lane & 3;    // float4 index within 16 features

    const int base = g_rowptr[v];
    const int end  = g_rowptr[v + 1];

    float4 acc = make_float4(0.f, 0.f, 0.f, 0.f);
    #pragma unroll 2
    for (int i = base + g; i < end; i += 8) {
        int s = __ldg(&g_col[i]);
        float4 m = *reinterpret_cast<const float4*>(&g_hp[(long long)s * F_MID + c * 4]);
        acc.x += m.x; acc.y += m.y; acc.z += m.z; acc.w += m.w;
    }
    #pragma unroll
    for (int d = 4; d < 32; d <<= 1) {
        acc.x += __shfl_xor_sync(0xffffffffu, acc.x, d);
        acc.y += __shfl_xor_sync(0xffffffffu, acc.y, d);
        acc.z += __shfl_xor_sync(0xffffffffu, acc.z, d);
        acc.w += __shfl_xor_sync(0xffffffffu, acc.w, d);
    }
    if (lane < 4) {
        float4 self = *reinterpret_cast<const float4*>(&g_hp[(long long)v * F_MID + lane * 4]);
        acc.x += self.x; acc.y += self.y; acc.z += self.z; acc.w += self.w;
        float dv = g_dinv[v];
        float4 bb = *reinterpret_cast<const float4*>(&bias[lane * 4]);
        float4 o;
        o.x = fmaxf(acc.x * dv + bb.x, 0.f) * dv;
        o.y = fmaxf(acc.y * dv + bb.y, 0.f) * dv;
        o.z = fmaxf(acc.z * dv + bb.z, 0.f) * dv;
        o.w = fmaxf(acc.w * dv + bb.w, 0.f) * dv;
        *reinterpret_cast<float4*>(&g_h1p[(long long)v * F_MID + lane * 4]) = o;
    }
}

// ---------------- layer-2 aggregation FUSED with output GEMM + log_softmax --
// s2 = dinv * (sum_{src} h1p[src] + h1p[v]); out = log_softmax(s2 @ W2 + b2)
__global__ __launch_bounds__(256) void k_agg2_out(const float* __restrict__ W2,
                                                 const float* __restrict__ b2,
                                                 float* __restrict__ out, int n) {
    __shared__ float W2s[F_MID * F_OUT];  // 1024 floats
    {
        int tid = threadIdx.x;
        for (int i = tid; i < F_MID * F_OUT; i += 256) W2s[i] = W2[i];
    }
    __syncthreads();

    const int warp = (blockIdx.x * blockDim.x + threadIdx.x) >> 5;
    const int lane = threadIdx.x & 31;
    if (warp >= n) return;
    const int v = warp;
    const int g = lane >> 2;
    const int c = lane & 3;

    const int base = g_rowptr[v];
    const int end  = g_rowptr[v + 1];

    float4 acc = make_float4(0.f, 0.f, 0.f, 0.f);
    #pragma unroll 2
    for (int i = base + g; i < end; i += 8) {
        int s = __ldg(&g_col[i]);
        float4 m = *reinterpret_cast<const float4*>(&g_h1p[(long long)s * F_MID + c * 4]);
        acc.x += m.x; acc.y += m.y; acc.z += m.z; acc.w += m.w;
    }
    #pragma unroll
    for (int d = 4; d < 32; d <<= 1) {
        acc.x += __shfl_xor_sync(0xffffffffu, acc.x, d);
        acc.y += __shfl_xor_sync(0xffffffffu, acc.y, d);
        acc.z += __shfl_xor_sync(0xffffffffu, acc.z, d);
        acc.w += __shfl_xor_sync(0xffffffffu, acc.w, d);
    }
    if (lane < 4) {  // finalize s2 in lanes 0..3 (lane j holds feats 4j..4j+3)
        float4 self = *reinterpret_cast<const float4*>(&g_h1p[(long long)v * F_MID + lane * 4]);
        float dv = g_dinv[v];
        acc.x = (acc.x + self.x) * dv;
        acc.y = (acc.y + self.y) * dv;
        acc.z = (acc.z + self.z) * dv;
        acc.w = (acc.w + self.w) * dv;
    }
    // broadcast the 16 s2 values to all lanes
    float s2[F_MID];
    #pragma unroll
    for (int j = 0; j < 4; j++) {
        s2[4 * j + 0] = __shfl_sync(0xffffffffu, acc.x, j);
        s2[4 * j + 1] = __shfl_sync(0xffffffffu, acc.y, j);
        s2[4 * j + 2] = __shfl_sync(0xffffffffu, acc.z, j);
        s2[4 * j + 3] = __shfl_sync(0xffffffffu, acc.w, j);
    }
    // output GEMM: each lane computes feats (lane) and (lane+32)
    float a = b2[lane];
    float b = b2[lane + 32];
    #pragma unroll
    for (int f = 0; f < F_MID; f++) {
        a = fmaf(s2[f], W2s[f * F_OUT + lane], a);
        b = fmaf(s2[f], W2s[f * F_OUT + lane + 32], b);
    }
    float M = fmaxf(a, b);
    #pragma unroll
    for (int d = 16; d > 0; d >>= 1) M = fmaxf(M, __shfl_xor_sync(0xffffffffu, M, d));
    float sum = expf(a - M) + expf(b - M);
    #pragma unroll
    for (int d = 16; d > 0; d >>= 1) sum += __shfl_xor_sync(0xffffffffu, sum, d);
    float lz = M + logf(sum);
    out[(long long)v * F_OUT + lane]      = a - lz;
    out[(long long)v * F_OUT + lane + 32] = b - lz;
}

// ---------------- launch (fork/join: gemm+scale overlap CSR build) ----------
extern "C" void kernel_launch(void* const* d_in, const int* in_sizes, int n_in,
                              void* d_out, int out_size) {
    const float* x  = (const float*)d_in[0];
    const void*  ei = d_in[1];
    const float* W1 = (const float*)d_in[2];
    const float* b1 = (const float*)d_in[3];
    const float* W2 = (const float*)d_in[4];
    const float* b2 = (const float*)d_in[5];
    float*       out = (float*)d_out;

    const int n = in_sizes[0] / F_IN;          // 100000
    const int E = in_sizes[1] / 2;             // 3200000

    const int B = 256;
    const int nodeGrid  = (n + B - 1) / B;
    const int hexGrid   = (int)(((long long)E / 16 + B) / B);  // 16 edges / thread
    const int tiles     = (n + 1023) / 1024;
    const int warpGrid  = (n + 7) / 8;         // 8 warps per 256-thread block
    const int scaleGrid = (n * 4 + B - 1) / B;

    // Persistent side stream + events. Created on the first (non-capturing)
    // correctness call; reused thereafter. Work launched is identical on
    // every call — this caches host handles only, never skips device work.
    static cudaStream_t s1 = nullptr;
    static cudaEvent_t evFork = nullptr, evScan = nullptr, evJoin = nullptr;
    if (s1 == nullptr) {
        cudaStreamCreateWithFlags(&s1, cudaStreamNonBlocking);
        cudaEventCreateWithFlags(&evFork, cudaEventDisableTiming);
        cudaEventCreateWithFlags(&evScan, cudaEventDisableTiming);
        cudaEventCreateWithFlags(&evJoin, cudaEventDisableTiming);
    }

    // Fork: gemm1 (independent of edges) runs on s1 while the CSR build
    // chain runs on the main stream.
    cudaEventRecord(evFork, 0);
    cudaStreamWaitEvent(s1, evFork, 0);
    k_gemm1<<<(n + 255) / 256, B, 0, s1>>>(x, W1, n);

    k_init_detect<<<nodeGrid, B>>>((const long long*)ei, n);
    k_count<<<hexGrid, B>>>(ei, E);
    k_scanAll<<<tiles, 1024>>>(n);
    cudaEventRecord(evScan, 0);          // dinv ready

    // scale on side stream (needs gemm + dinv), overlaps k_fill on main
    cudaStreamWaitEvent(s1, evScan, 0);
    k_scale<<<scaleGrid, B, 0, s1>>>(n);
    cudaEventRecord(evJoin, s1);

    k_fill<<<hexGrid, B>>>(ei, E);

    // Join: aggregation needs scaled g_hp and the CSR.
    cudaStreamWaitEvent(0, evJoin, 0);
    k_agg1<<<warpGrid, B>>>(b1, n);
    k_agg2_out<<<warpGrid, B>>>(W2, b2, out, n);
}